// round 15
// baseline (speedup 1.0000x reference)
#include <cuda_runtime.h>

#define NB 16384
#define NP 8
#define ND 64
#define NH 128
#define NOPS_ 37
#define OPSTART 16
#define NITER_ 16
#define NCAS 7

#define NBLK_R1 128            // route1 grid (NB / 128 threads)
#define GRID_BLOCKS 740        // measured-best fused config
#define WS_STRIDE 1632         // per-row workspace floats: max(8*132, 3*8*68)
#define HS_STRIDE 132          // padded hidden row
#define QK_STRIDE 68           // padded qkv row

typedef unsigned long long ull;

// ---- scratch (static device globals; no allocation) ----
__device__ int g_op[NB];
__device__ int g_carry[NB];
__device__ int g_div[NB];
__device__ int g_mod[NB];
__device__ int g_dense[NB];
__device__ int g_bh[NBLK_R1][NOPS_];   // per-block op histograms (route1)
__device__ int g_opcnt[NOPS_];
__device__ int g_base[NOPS_];          // per-op base within destination list
__device__ int g_cursor[NOPS_];
__device__ int g_cnt[4];               // sizes: carry, div, mod, dense
__device__ int g_claim[4];

__device__ __forceinline__ bool is_carry_op(int op) {
    return (op == 0) | (op == 1) | (op == 2) |
           (op == 10) | (op == 11) | (op == 12) | (op == 13);
}

// Pass 1: per-row argmax opcode via vectorized LDG.128 (channels 16..52 are
// float4-aligned). Per-block smem histogram written to g_bh with plain
// stores (all 37 slots) -> NO global atomics, NO pre-zero kernel needed.
__global__ void route1_kernel(const float* __restrict__ x) {
    __shared__ int hist[NOPS_];
    int t = threadIdx.x;
    if (t < NOPS_) hist[t] = 0;
    __syncthreads();
    int b = blockIdx.x * blockDim.x + t;
    const float4* p4 = (const float4*)(x + (size_t)b * NP * ND + OPSTART);
    float v[40];
    #pragma unroll
    for (int j = 0; j < 10; j++) {
        float4 q = __ldg(&p4[j]);
        v[4 * j + 0] = q.x; v[4 * j + 1] = q.y;
        v[4 * j + 2] = q.z; v[4 * j + 3] = q.w;
    }
    float best = v[0];
    int op = 0;
    #pragma unroll
    for (int j = 1; j < NOPS_; j++) {
        if (v[j] > best) { best = v[j]; op = j; }   // strict >: first-index argmax
    }
    g_op[b] = op;
    atomicAdd(&hist[op], 1);
    __syncthreads();
    if (t < NOPS_) g_bh[blockIdx.x][t] = hist[t];   // plain store, always written
}

// Column-sum the per-block histograms (37 threads, independent loads),
// then thread 0 runs the tiny 37-op base scan. Also zeroes cursor/claim
// (consumed only by the later route2/fused launches).
__global__ void scan_kernel() {
    __shared__ int cnt[NOPS_];
    int t = threadIdx.x;
    if (t < NOPS_) {
        int s = 0;
        #pragma unroll 8
        for (int k = 0; k < NBLK_R1; k++) s += g_bh[k][t];
        cnt[t] = s;
        g_opcnt[t] = s;
        g_cursor[t] = 0;
    }
    if (t < 4) g_claim[t] = 0;
    __syncthreads();
    if (t == 0) {
        int cb = 0, db = 0;
        for (int op = 0; op < NOPS_; op++) {
            int c = cnt[op];
            if (is_carry_op(op))          { g_base[op] = cb; cb += c; }
            else if (op == 3 || op == 4)  { g_base[op] = 0; }
            else                          { g_base[op] = db; db += c; }
        }
        g_cnt[0] = cb;
        g_cnt[1] = cnt[3];
        g_cnt[2] = cnt[4];
        g_cnt[3] = db;
    }
}

// Pass 2: scatter rows into op-sorted pool lists. Per-block chunk
// reservation: one global atomic per op per block, then smem-ranked scatter.
__global__ void route2_kernel() {
    __shared__ int hist[NOPS_];
    __shared__ int bbase[NOPS_];
    __shared__ int cur[NOPS_];
    int t = threadIdx.x;
    if (t < NOPS_) { hist[t] = 0; cur[t] = 0; }
    __syncthreads();
    int b = blockIdx.x * blockDim.x + t;
    int op = g_op[b];
    atomicAdd(&hist[op], 1);
    __syncthreads();
    if (t < NOPS_ && hist[t] > 0)
        bbase[t] = atomicAdd(&g_cursor[t], hist[t]);
    __syncthreads();
    int pos = bbase[op] + atomicAdd(&cur[op], 1) + g_base[op];
    if (is_carry_op(op))  g_carry[pos] = b;
    else if (op == 3)     g_div[pos] = b;
    else if (op == 4)     g_mod[pos] = b;
    else                  g_dense[pos] = b;
}

// ---- packed fp32x2 primitives (FFMA2 path; bit-identical fp32 numerics) ----
__device__ __forceinline__ ull pack2(float x, float y) {
    ull r;
    asm("mov.b64 %0, {%1, %2};"
        : "=l"(r) : "r"(__float_as_uint(x)), "r"(__float_as_uint(y)));
    return r;
}
__device__ __forceinline__ ull fma2(ull a, ull b, ull c) {
    ull d;
    asm("fma.rn.f32x2 %0, %1, %2, %3;" : "=l"(d) : "l"(a), "l"(b), "l"(c));
    return d;
}
__device__ __forceinline__ float2 unpack2(ull v) {
    unsigned int lo, hi;
    asm("mov.b64 {%0, %1}, %2;" : "=r"(lo), "=r"(hi) : "l"(v));
    return make_float2(__uint_as_float(lo), __uint_as_float(hi));
}

// ---------------------------------------------------------------------------
// Warp-level FFN with residual; one warp owns one row. (Measured-best layout:
// conflict-free 16B-stride stores, broadcast LDS reads, FFMA2 accumulators.)
// ---------------------------------------------------------------------------
__device__ __forceinline__ void ffn_w(
    float (*xs)[ND], float* ws,
    const float* __restrict__ W1, const float* __restrict__ b1,
    const float* __restrict__ W2, const float* __restrict__ b2, int lane)
{
    // ---- layer 1: h = relu(x @ W1 + b1); lane owns h columns [4*lane, +4) ----
    {
        const int h0 = lane * 4;
        float4 bb = __ldg((const float4*)(b1 + h0));
        ull acc[NP][2];
        {
            ull b01 = pack2(bb.x, bb.y), b23 = pack2(bb.z, bb.w);
            #pragma unroll
            for (int p = 0; p < NP; p++) { acc[p][0] = b01; acc[p][1] = b23; }
        }
        #pragma unroll 2
        for (int d4 = 0; d4 < ND; d4 += 4) {
            ulonglong2 w0 = __ldg((const ulonglong2*)(W1 + (d4 + 0) * NH + h0));
            ulonglong2 w1 = __ldg((const ulonglong2*)(W1 + (d4 + 1) * NH + h0));
            ulonglong2 w2 = __ldg((const ulonglong2*)(W1 + (d4 + 2) * NH + h0));
            ulonglong2 w3 = __ldg((const ulonglong2*)(W1 + (d4 + 3) * NH + h0));
            #pragma unroll
            for (int p = 0; p < NP; p++) {
                float4 xv = *(const float4*)&xs[p][d4];
                ull xx;
                xx = pack2(xv.x, xv.x);
                acc[p][0] = fma2(xx, w0.x, acc[p][0]);
                acc[p][1] = fma2(xx, w0.y, acc[p][1]);
                xx = pack2(xv.y, xv.y);
                acc[p][0] = fma2(xx, w1.x, acc[p][0]);
                acc[p][1] = fma2(xx, w1.y, acc[p][1]);
                xx = pack2(xv.z, xv.z);
                acc[p][0] = fma2(xx, w2.x, acc[p][0]);
                acc[p][1] = fma2(xx, w2.y, acc[p][1]);
                xx = pack2(xv.w, xv.w);
                acc[p][0] = fma2(xx, w3.x, acc[p][0]);
                acc[p][1] = fma2(xx, w3.y, acc[p][1]);
            }
        }
        #pragma unroll
        for (int p = 0; p < NP; p++) {
            float2 a = unpack2(acc[p][0]), b = unpack2(acc[p][1]);
            float4 o;
            o.x = fmaxf(a.x, 0.f); o.y = fmaxf(a.y, 0.f);
            o.z = fmaxf(b.x, 0.f); o.w = fmaxf(b.y, 0.f);
            *(float4*)&ws[p * HS_STRIDE + h0] = o;
        }
    }
    __syncwarp();
    // ---- layer 2: x += h @ W2 + b2; lane owns 4 dd cols, half the p rows ----
    {
        const int dd0 = (lane & 15) * 4;
        const int ph  = (lane >> 4) * 4;
        ull acc[4][2];
        #pragma unroll
        for (int i = 0; i < 4; i++) { acc[i][0] = 0ull; acc[i][1] = 0ull; }
        #pragma unroll 2
        for (int h4 = 0; h4 < NH; h4 += 4) {
            ulonglong2 w0 = __ldg((const ulonglong2*)(W2 + (h4 + 0) * ND + dd0));
            ulonglong2 w1 = __ldg((const ulonglong2*)(W2 + (h4 + 1) * ND + dd0));
            ulonglong2 w2 = __ldg((const ulonglong2*)(W2 + (h4 + 2) * ND + dd0));
            ulonglong2 w3 = __ldg((const ulonglong2*)(W2 + (h4 + 3) * ND + dd0));
            #pragma unroll
            for (int i = 0; i < 4; i++) {
                float4 hv = *(const float4*)&ws[(ph + i) * HS_STRIDE + h4];
                ull xx;
                xx = pack2(hv.x, hv.x);
                acc[i][0] = fma2(xx, w0.x, acc[i][0]);
                acc[i][1] = fma2(xx, w0.y, acc[i][1]);
                xx = pack2(hv.y, hv.y);
                acc[i][0] = fma2(xx, w1.x, acc[i][0]);
                acc[i][1] = fma2(xx, w1.y, acc[i][1]);
                xx = pack2(hv.z, hv.z);
                acc[i][0] = fma2(xx, w2.x, acc[i][0]);
                acc[i][1] = fma2(xx, w2.y, acc[i][1]);
                xx = pack2(hv.w, hv.w);
                acc[i][0] = fma2(xx, w3.x, acc[i][0]);
                acc[i][1] = fma2(xx, w3.y, acc[i][1]);
            }
        }
        float4 bb = __ldg((const float4*)(b2 + dd0));
        #pragma unroll
        for (int i = 0; i < 4; i++) {
            float2 a = unpack2(acc[i][0]), b = unpack2(acc[i][1]);
            float4 cur = *(const float4*)&xs[ph + i][dd0];
            cur.x += a.x + bb.x; cur.y += a.y + bb.y;
            cur.z += b.x + bb.z; cur.w += b.y + bb.w;
            *(float4*)&xs[ph + i][dd0] = cur;
        }
    }
    __syncwarp();
}

// ---------------------------------------------------------------------------
// Warp-level carry attention, FUSED q/k/v (packs shared across 3 matrices).
// ws layout: qs @ 0, ks @ 544, vs @ 1088, each 8 rows of stride 68.
// ---------------------------------------------------------------------------
__device__ __forceinline__ void attn_w(
    float (*xs)[ND], float* ws, float (*sc)[8],
    const float* __restrict__ Wq, const float* __restrict__ Wk,
    const float* __restrict__ Wv, int lane)
{
    const int c0 = lane * 2;
    float* qsm = ws;
    float* ksm = ws + 544;
    float* vsm = ws + 1088;
    {
        ull aq[NP], ak[NP], av[NP];
        #pragma unroll
        for (int p = 0; p < NP; p++) { aq[p] = 0ull; ak[p] = 0ull; av[p] = 0ull; }
        #pragma unroll 2
        for (int d4 = 0; d4 < ND; d4 += 4) {
            ull wq0 = __ldg((const ull*)(Wq + (d4 + 0) * ND + c0));
            ull wq1 = __ldg((const ull*)(Wq + (d4 + 1) * ND + c0));
            ull wq2 = __ldg((const ull*)(Wq + (d4 + 2) * ND + c0));
            ull wq3 = __ldg((const ull*)(Wq + (d4 + 3) * ND + c0));
            ull wk0 = __ldg((const ull*)(Wk + (d4 + 0) * ND + c0));
            ull wk1 = __ldg((const ull*)(Wk + (d4 + 1) * ND + c0));
            ull wk2 = __ldg((const ull*)(Wk + (d4 + 2) * ND + c0));
            ull wk3 = __ldg((const ull*)(Wk + (d4 + 3) * ND + c0));
            ull wv0 = __ldg((const ull*)(Wv + (d4 + 0) * ND + c0));
            ull wv1 = __ldg((const ull*)(Wv + (d4 + 1) * ND + c0));
            ull wv2 = __ldg((const ull*)(Wv + (d4 + 2) * ND + c0));
            ull wv3 = __ldg((const ull*)(Wv + (d4 + 3) * ND + c0));
            #pragma unroll
            for (int p = 0; p < NP; p++) {
                float4 xv = *(const float4*)&xs[p][d4];
                ull xx;
                xx = pack2(xv.x, xv.x);
                aq[p] = fma2(xx, wq0, aq[p]);
                ak[p] = fma2(xx, wk0, ak[p]);
                av[p] = fma2(xx, wv0, av[p]);
                xx = pack2(xv.y, xv.y);
                aq[p] = fma2(xx, wq1, aq[p]);
                ak[p] = fma2(xx, wk1, ak[p]);
                av[p] = fma2(xx, wv1, av[p]);
                xx = pack2(xv.z, xv.z);
                aq[p] = fma2(xx, wq2, aq[p]);
                ak[p] = fma2(xx, wk2, ak[p]);
                av[p] = fma2(xx, wv2, av[p]);
                xx = pack2(xv.w, xv.w);
                aq[p] = fma2(xx, wq3, aq[p]);
                ak[p] = fma2(xx, wk3, ak[p]);
                av[p] = fma2(xx, wv3, av[p]);
            }
        }
        #pragma unroll
        for (int p = 0; p < NP; p++) {
            float2 q = unpack2(aq[p]);
            float2 k = unpack2(ak[p]);
            float2 v = unpack2(av[p]);
            *(float2*)&qsm[p * QK_STRIDE + c0] = q;
            *(float2*)&ksm[p * QK_STRIDE + c0] = k;
            *(float2*)&vsm[p * QK_STRIDE + c0] = v;
        }
    }
    __syncwarp();
    // ---- scores: each lane does 2 of the 64 (p,q') dots ----
    #pragma unroll
    for (int j = 0; j < 2; j++) {
        int idx = lane + 32 * j;
        int p = idx >> 3, qq = idx & 7;
        float s = 0.f;
        #pragma unroll
        for (int d4 = 0; d4 < ND; d4 += 4) {
            float4 qv = *(const float4*)&qsm[p * QK_STRIDE + d4];
            float4 kv = *(const float4*)&ksm[qq * QK_STRIDE + d4];
            s = fmaf(qv.x, kv.x, s); s = fmaf(qv.y, kv.y, s);
            s = fmaf(qv.z, kv.z, s); s = fmaf(qv.w, kv.w, s);
        }
        sc[p][qq] = s * 0.125f;
    }
    __syncwarp();
    // ---- softmax over q' (lanes 0-7, one row each) ----
    if (lane < 8) {
        float m = sc[lane][0];
        #pragma unroll
        for (int q = 1; q < 8; q++) m = fmaxf(m, sc[lane][q]);
        float e[8], sum = 0.f;
        #pragma unroll
        for (int q = 0; q < 8; q++) { e[q] = __expf(sc[lane][q] - m); sum += e[q]; }
        float inv = 1.0f / sum;
        #pragma unroll
        for (int q = 0; q < 8; q++) sc[lane][q] = e[q] * inv;
    }
    __syncwarp();
    // ---- out: xs += s @ v (lane owns column pair c0) ----
    {
        ull vq[8];
        #pragma unroll
        for (int q = 0; q < 8; q++)
            vq[q] = *(const ull*)&vsm[q * QK_STRIDE + c0];
        #pragma unroll
        for (int p = 0; p < NP; p++) {
            float4 s0 = *(const float4*)&sc[p][0];
            float4 s1 = *(const float4*)&sc[p][4];
            ull a = 0ull;
            a = fma2(pack2(s0.x, s0.x), vq[0], a);
            a = fma2(pack2(s0.y, s0.y), vq[1], a);
            a = fma2(pack2(s0.z, s0.z), vq[2], a);
            a = fma2(pack2(s0.w, s0.w), vq[3], a);
            a = fma2(pack2(s1.x, s1.x), vq[4], a);
            a = fma2(pack2(s1.y, s1.y), vq[5], a);
            a = fma2(pack2(s1.z, s1.z), vq[6], a);
            a = fma2(pack2(s1.w, s1.w), vq[7], a);
            float2 r = unpack2(a);
            float2 cur = *(const float2*)&xs[p][c0];
            cur.x += r.x; cur.y += r.y;
            *(float2*)&xs[p][c0] = cur;
        }
    }
    __syncwarp();
}

// ---------------------------------------------------------------------------
// ONE fused compute kernel: four work-stealing pools, heaviest first.
// (Measured-best: claim 1 row per atomic in every pool, GRID 740.)
// ---------------------------------------------------------------------------
__global__ void __launch_bounds__(128) fused_kernel(
    const float* __restrict__ xin, float* __restrict__ xout,
    const float* __restrict__ Wi1, const float* __restrict__ bi1,
    const float* __restrict__ Wi2, const float* __restrict__ bi2,
    const float* __restrict__ Wq, const float* __restrict__ Wk,
    const float* __restrict__ Wv,
    const float* __restrict__ Wc1, const float* __restrict__ bc1,
    const float* __restrict__ Wc2, const float* __restrict__ bc2,
    const float* __restrict__ Wd1, const float* __restrict__ bd1,
    const float* __restrict__ Wd2, const float* __restrict__ bd2,
    const float* __restrict__ Wm1, const float* __restrict__ bm1,
    const float* __restrict__ Wm2, const float* __restrict__ bm2,
    const float* __restrict__ Wf1, const float* __restrict__ bf1,
    const float* __restrict__ Wf2, const float* __restrict__ bf2)
{
    __shared__ __align__(16) float xs[4][NP][ND];
    __shared__ __align__(16) float ws[4][WS_STRIDE];
    __shared__ __align__(16) float sc[4][NP][8];
    const int w = threadIdx.x >> 5, lane = threadIdx.x & 31;
    float (*xsr)[ND] = xs[w];
    float* wsr = ws[w];
    float4* mine = (float4*)&xsr[0][0];

    // ---------------- pool 0: carry cascade rows ----------------
    const int n0 = g_cnt[0];
    for (;;) {
        int idx = 0;
        if (lane == 0) idx = atomicAdd(&g_claim[0], 1);
        idx = __shfl_sync(0xffffffffu, idx, 0);
        if (idx >= n0) break;
        const int b = g_carry[idx];
        const int op = g_op[b];
        const float4* src = (const float4*)(xin + (size_t)b * NP * ND);
        #pragma unroll
        for (int j = 0; j < 4; j++) mine[lane + 32 * j] = src[lane + 32 * j];
        __syncwarp();
        ffn_w(xsr, wsr, Wi1 + (size_t)op * ND * NH, bi1 + op * NH,
              Wi2 + (size_t)op * NH * ND, bi2 + op * ND, lane);
        {
            const float* W1 = Wc1 + (size_t)op * ND * NH;
            const float* B1 = bc1 + op * NH;
            const float* W2 = Wc2 + (size_t)op * NH * ND;
            const float* B2 = bc2 + op * ND;
            #pragma unroll 1
            for (int it = 0; it < NCAS; it++) {
                attn_w(xsr, wsr, sc[w], Wq, Wk, Wv, lane);
                ffn_w(xsr, wsr, W1, B1, W2, B2, lane);
            }
        }
        ffn_w(xsr, wsr, Wf1 + (size_t)op * ND * NH, bf1 + op * NH,
              Wf2 + (size_t)op * NH * ND, bf2 + op * ND, lane);
        float4* dst = (float4*)(xout + (size_t)b * NP * ND);
        #pragma unroll
        for (int j = 0; j < 4; j++) dst[lane + 32 * j] = mine[lane + 32 * j];
        __syncwarp();
    }
    // ---------------- pool 1: DIV chain rows ----------------
    const int n1 = g_cnt[1];
    for (;;) {
        int idx = 0;
        if (lane == 0) idx = atomicAdd(&g_claim[1], 1);
        idx = __shfl_sync(0xffffffffu, idx, 0);
        if (idx >= n1) break;
        const int b = g_div[idx];
        const float4* src = (const float4*)(xin + (size_t)b * NP * ND);
        #pragma unroll
        for (int j = 0; j < 4; j++) mine[lane + 32 * j] = src[lane + 32 * j];
        __syncwarp();
        ffn_w(xsr, wsr, Wi1 + (size_t)3 * ND * NH, bi1 + 3 * NH,
              Wi2 + (size_t)3 * NH * ND, bi2 + 3 * ND, lane);
        #pragma unroll 1
        for (int i = 0; i < NITER_; i++)
            ffn_w(xsr, wsr, Wd1 + (size_t)i * ND * NH, bd1 + i * NH,
                  Wd2 + (size_t)i * NH * ND, bd2 + i * ND, lane);
        ffn_w(xsr, wsr, Wf1 + (size_t)3 * ND * NH, bf1 + 3 * NH,
              Wf2 + (size_t)3 * NH * ND, bf2 + 3 * ND, lane);
        float4* dst = (float4*)(xout + (size_t)b * NP * ND);
        #pragma unroll
        for (int j = 0; j < 4; j++) dst[lane + 32 * j] = mine[lane + 32 * j];
        __syncwarp();
    }
    // ---------------- pool 2: MOD chain rows ----------------
    const int n2 = g_cnt[2];
    for (;;) {
        int idx = 0;
        if (lane == 0) idx = atomicAdd(&g_claim[2], 1);
        idx = __shfl_sync(0xffffffffu, idx, 0);
        if (idx >= n2) break;
        const int b = g_mod[idx];
        const float4* src = (const float4*)(xin + (size_t)b * NP * ND);
        #pragma unroll
        for (int j = 0; j < 4; j++) mine[lane + 32 * j] = src[lane + 32 * j];
        __syncwarp();
        ffn_w(xsr, wsr, Wi1 + (size_t)4 * ND * NH, bi1 + 4 * NH,
              Wi2 + (size_t)4 * NH * ND, bi2 + 4 * ND, lane);
        #pragma unroll 1
        for (int i = 0; i < NITER_; i++)
            ffn_w(xsr, wsr, Wm1 + (size_t)i * ND * NH, bm1 + i * NH,
                  Wm2 + (size_t)i * NH * ND, bm2 + i * ND, lane);
        ffn_w(xsr, wsr, Wf1 + (size_t)4 * ND * NH, bf1 + 4 * NH,
              Wf2 + (size_t)4 * NH * ND, bf2 + 4 * ND, lane);
        float4* dst = (float4*)(xout + (size_t)b * NP * ND);
        #pragma unroll
        for (int j = 0; j < 4; j++) dst[lane + 32 * j] = mine[lane + 32 * j];
        __syncwarp();
    }
    // ---------------- pool 3: dense rows (stage1 + final only) ----------------
    const int n3 = g_cnt[3];
    for (;;) {
        int idx = 0;
        if (lane == 0) idx = atomicAdd(&g_claim[3], 1);
        idx = __shfl_sync(0xffffffffu, idx, 0);
        if (idx >= n3) break;
        const int b = g_dense[idx];
        const int op = g_op[b];
        const float4* src = (const float4*)(xin + (size_t)b * NP * ND);
        #pragma unroll
        for (int j = 0; j < 4; j++) mine[lane + 32 * j] = src[lane + 32 * j];
        __syncwarp();
        ffn_w(xsr, wsr, Wi1 + (size_t)op * ND * NH, bi1 + op * NH,
              Wi2 + (size_t)op * NH * ND, bi2 + op * ND, lane);
        ffn_w(xsr, wsr, Wf1 + (size_t)op * ND * NH, bf1 + op * NH,
              Wf2 + (size_t)op * NH * ND, bf2 + op * ND, lane);
        float4* dst = (float4*)(xout + (size_t)b * NP * ND);
        #pragma unroll
        for (int j = 0; j < 4; j++) dst[lane + 32 * j] = mine[lane + 32 * j];
        __syncwarp();
    }
}

// ---------------------------------------------------------------------------
// Launch sequence (graph-capturable; scratch is static device globals).
// 4 launches: route1 -> scan -> route2 -> fused.
// ---------------------------------------------------------------------------
extern "C" void kernel_launch(void* const* d_in, const int* in_sizes, int n_in,
                              void* d_out, int out_size)
{
    const float* x   = (const float*)d_in[0];
    const float* Wi1 = (const float*)d_in[1];
    const float* bi1 = (const float*)d_in[2];
    const float* Wi2 = (const float*)d_in[3];
    const float* bi2 = (const float*)d_in[4];
    const float* Wq  = (const float*)d_in[5];
    const float* Wk  = (const float*)d_in[6];
    const float* Wv  = (const float*)d_in[7];
    const float* Wc1 = (const float*)d_in[8];
    const float* bc1 = (const float*)d_in[9];
    const float* Wc2 = (const float*)d_in[10];
    const float* bc2 = (const float*)d_in[11];
    const float* Wd1 = (const float*)d_in[12];
    const float* bd1 = (const float*)d_in[13];
    const float* Wd2 = (const float*)d_in[14];
    const float* bd2 = (const float*)d_in[15];
    const float* Wm1 = (const float*)d_in[16];
    const float* bm1 = (const float*)d_in[17];
    const float* Wm2 = (const float*)d_in[18];
    const float* bm2 = (const float*)d_in[19];
    const float* Wf1 = (const float*)d_in[20];
    const float* bf1 = (const float*)d_in[21];
    const float* Wf2 = (const float*)d_in[22];
    const float* bf2 = (const float*)d_in[23];
    float* out = (float*)d_out;

    route1_kernel<<<NBLK_R1, 128>>>(x);
    scan_kernel<<<1, 64>>>();
    route2_kernel<<<NB / 128, 128>>>();
    fused_kernel<<<GRID_BLOCKS, 128>>>(
        x, out,
        Wi1, bi1, Wi2, bi2,
        Wq, Wk, Wv, Wc1, bc1, Wc2, bc2,
        Wd1, bd1, Wd2, bd2, Wm1, bm1, Wm2, bm2,
        Wf1, bf1, Wf2, bf2);
}

// round 16
// speedup vs baseline: 1.0505x; 1.0505x over previous
#include <cuda_runtime.h>

#define NB 16384
#define NP 8
#define ND 64
#define NH 128
#define NOPS_ 37
#define OPSTART 16
#define NITER_ 16
#define NCAS 7

#define NBLK_R1 128            // route1 grid (NB / 128 threads)
#define GRID_BLOCKS 740        // measured-best fused config
#define WS_STRIDE 1632         // per-row workspace floats: max(8*132, 3*8*68)
#define HS_STRIDE 132          // padded hidden row
#define QK_STRIDE 68           // padded qkv row

typedef unsigned long long ull;

// ---- scratch (static device globals; no allocation) ----
__device__ int g_op[NB];
__device__ int g_carry[NB];
__device__ int g_div[NB];
__device__ int g_mod[NB];
__device__ int g_dense[NB];
__device__ int g_bh[NBLK_R1][NOPS_];   // per-block op histograms (route1)
__device__ int g_opcnt[NOPS_];
__device__ int g_base[NOPS_];          // per-op base within destination list
__device__ int g_cursor[NOPS_];
__device__ int g_cnt[4];               // sizes: carry, div, mod, dense
__device__ int g_claim[4];

__device__ __forceinline__ bool is_carry_op(int op) {
    return (op == 0) | (op == 1) | (op == 2) |
           (op == 10) | (op == 11) | (op == 12) | (op == 13);
}

// Pass 1: per-row argmax opcode via vectorized LDG.128 (channels 16..52 are
// float4-aligned). Per-block smem histogram written to g_bh with plain
// stores (all 37 slots) -> NO global atomics, NO pre-zero kernel needed.
__global__ void route1_kernel(const float* __restrict__ x) {
    __shared__ int hist[NOPS_];
    int t = threadIdx.x;
    if (t < NOPS_) hist[t] = 0;
    __syncthreads();
    int b = blockIdx.x * blockDim.x + t;
    const float4* p4 = (const float4*)(x + (size_t)b * NP * ND + OPSTART);
    float v[40];
    #pragma unroll
    for (int j = 0; j < 10; j++) {
        float4 q = __ldg(&p4[j]);
        v[4 * j + 0] = q.x; v[4 * j + 1] = q.y;
        v[4 * j + 2] = q.z; v[4 * j + 3] = q.w;
    }
    float best = v[0];
    int op = 0;
    #pragma unroll
    for (int j = 1; j < NOPS_; j++) {
        if (v[j] > best) { best = v[j]; op = j; }   // strict >: first-index argmax
    }
    g_op[b] = op;
    atomicAdd(&hist[op], 1);
    __syncthreads();
    if (t < NOPS_) g_bh[blockIdx.x][t] = hist[t];   // plain store, always written
}

// Column-sum the per-block histograms (37 threads, independent loads),
// then thread 0 runs the tiny 37-op base scan. Also zeroes cursor/claim.
__global__ void scan_kernel() {
    __shared__ int cnt[NOPS_];
    int t = threadIdx.x;
    if (t < NOPS_) {
        int s = 0;
        #pragma unroll 8
        for (int k = 0; k < NBLK_R1; k++) s += g_bh[k][t];
        cnt[t] = s;
        g_opcnt[t] = s;
        g_cursor[t] = 0;
    }
    if (t < 4) g_claim[t] = 0;
    __syncthreads();
    if (t == 0) {
        int cb = 0, db = 0;
        for (int op = 0; op < NOPS_; op++) {
            int c = cnt[op];
            if (is_carry_op(op))          { g_base[op] = cb; cb += c; }
            else if (op == 3 || op == 4)  { g_base[op] = 0; }
            else                          { g_base[op] = db; db += c; }
        }
        g_cnt[0] = cb;
        g_cnt[1] = cnt[3];
        g_cnt[2] = cnt[4];
        g_cnt[3] = db;
    }
}

// Pass 2: scatter rows into op-sorted pool lists. Per-block chunk
// reservation: one global atomic per op per block, then smem-ranked scatter.
__global__ void route2_kernel() {
    __shared__ int hist[NOPS_];
    __shared__ int bbase[NOPS_];
    __shared__ int cur[NOPS_];
    int t = threadIdx.x;
    if (t < NOPS_) { hist[t] = 0; cur[t] = 0; }
    __syncthreads();
    int b = blockIdx.x * blockDim.x + t;
    int op = g_op[b];
    atomicAdd(&hist[op], 1);
    __syncthreads();
    if (t < NOPS_ && hist[t] > 0)
        bbase[t] = atomicAdd(&g_cursor[t], hist[t]);
    __syncthreads();
    int pos = bbase[op] + atomicAdd(&cur[op], 1) + g_base[op];
    if (is_carry_op(op))  g_carry[pos] = b;
    else if (op == 3)     g_div[pos] = b;
    else if (op == 4)     g_mod[pos] = b;
    else                  g_dense[pos] = b;
}

// ---- packed fp32x2 primitives (FFMA2 path; bit-identical fp32 numerics) ----
__device__ __forceinline__ ull pack2(float x, float y) {
    ull r;
    asm("mov.b64 %0, {%1, %2};"
        : "=l"(r) : "r"(__float_as_uint(x)), "r"(__float_as_uint(y)));
    return r;
}
__device__ __forceinline__ ull fma2(ull a, ull b, ull c) {
    ull d;
    asm("fma.rn.f32x2 %0, %1, %2, %3;" : "=l"(d) : "l"(a), "l"(b), "l"(c));
    return d;
}
__device__ __forceinline__ float2 unpack2(ull v) {
    unsigned int lo, hi;
    asm("mov.b64 {%0, %1}, %2;" : "=r"(lo), "=r"(hi) : "l"(v));
    return make_float2(__uint_as_float(lo), __uint_as_float(hi));
}

// ---------------------------------------------------------------------------
// Warp-level FFN with residual; one warp owns one row. (Measured-best layout:
// conflict-free 16B-stride stores, broadcast LDS reads, FFMA2 accumulators.)
// ---------------------------------------------------------------------------
__device__ __forceinline__ void ffn_w(
    float (*xs)[ND], float* ws,
    const float* __restrict__ W1, const float* __restrict__ b1,
    const float* __restrict__ W2, const float* __restrict__ b2, int lane)
{
    // ---- layer 1: h = relu(x @ W1 + b1); lane owns h columns [4*lane, +4) ----
    {
        const int h0 = lane * 4;
        float4 bb = __ldg((const float4*)(b1 + h0));
        ull acc[NP][2];
        {
            ull b01 = pack2(bb.x, bb.y), b23 = pack2(bb.z, bb.w);
            #pragma unroll
            for (int p = 0; p < NP; p++) { acc[p][0] = b01; acc[p][1] = b23; }
        }
        #pragma unroll 2
        for (int d4 = 0; d4 < ND; d4 += 4) {
            ulonglong2 w0 = __ldg((const ulonglong2*)(W1 + (d4 + 0) * NH + h0));
            ulonglong2 w1 = __ldg((const ulonglong2*)(W1 + (d4 + 1) * NH + h0));
            ulonglong2 w2 = __ldg((const ulonglong2*)(W1 + (d4 + 2) * NH + h0));
            ulonglong2 w3 = __ldg((const ulonglong2*)(W1 + (d4 + 3) * NH + h0));
            #pragma unroll
            for (int p = 0; p < NP; p++) {
                float4 xv = *(const float4*)&xs[p][d4];
                ull xx;
                xx = pack2(xv.x, xv.x);
                acc[p][0] = fma2(xx, w0.x, acc[p][0]);
                acc[p][1] = fma2(xx, w0.y, acc[p][1]);
                xx = pack2(xv.y, xv.y);
                acc[p][0] = fma2(xx, w1.x, acc[p][0]);
                acc[p][1] = fma2(xx, w1.y, acc[p][1]);
                xx = pack2(xv.z, xv.z);
                acc[p][0] = fma2(xx, w2.x, acc[p][0]);
                acc[p][1] = fma2(xx, w2.y, acc[p][1]);
                xx = pack2(xv.w, xv.w);
                acc[p][0] = fma2(xx, w3.x, acc[p][0]);
                acc[p][1] = fma2(xx, w3.y, acc[p][1]);
            }
        }
        #pragma unroll
        for (int p = 0; p < NP; p++) {
            float2 a = unpack2(acc[p][0]), b = unpack2(acc[p][1]);
            float4 o;
            o.x = fmaxf(a.x, 0.f); o.y = fmaxf(a.y, 0.f);
            o.z = fmaxf(b.x, 0.f); o.w = fmaxf(b.y, 0.f);
            *(float4*)&ws[p * HS_STRIDE + h0] = o;
        }
    }
    __syncwarp();
    // ---- layer 2: x += h @ W2 + b2; lane owns 4 dd cols, half the p rows ----
    {
        const int dd0 = (lane & 15) * 4;
        const int ph  = (lane >> 4) * 4;
        ull acc[4][2];
        #pragma unroll
        for (int i = 0; i < 4; i++) { acc[i][0] = 0ull; acc[i][1] = 0ull; }
        #pragma unroll 2
        for (int h4 = 0; h4 < NH; h4 += 4) {
            ulonglong2 w0 = __ldg((const ulonglong2*)(W2 + (h4 + 0) * ND + dd0));
            ulonglong2 w1 = __ldg((const ulonglong2*)(W2 + (h4 + 1) * ND + dd0));
            ulonglong2 w2 = __ldg((const ulonglong2*)(W2 + (h4 + 2) * ND + dd0));
            ulonglong2 w3 = __ldg((const ulonglong2*)(W2 + (h4 + 3) * ND + dd0));
            #pragma unroll
            for (int i = 0; i < 4; i++) {
                float4 hv = *(const float4*)&ws[(ph + i) * HS_STRIDE + h4];
                ull xx;
                xx = pack2(hv.x, hv.x);
                acc[i][0] = fma2(xx, w0.x, acc[i][0]);
                acc[i][1] = fma2(xx, w0.y, acc[i][1]);
                xx = pack2(hv.y, hv.y);
                acc[i][0] = fma2(xx, w1.x, acc[i][0]);
                acc[i][1] = fma2(xx, w1.y, acc[i][1]);
                xx = pack2(hv.z, hv.z);
                acc[i][0] = fma2(xx, w2.x, acc[i][0]);
                acc[i][1] = fma2(xx, w2.y, acc[i][1]);
                xx = pack2(hv.w, hv.w);
                acc[i][0] = fma2(xx, w3.x, acc[i][0]);
                acc[i][1] = fma2(xx, w3.y, acc[i][1]);
            }
        }
        float4 bb = __ldg((const float4*)(b2 + dd0));
        #pragma unroll
        for (int i = 0; i < 4; i++) {
            float2 a = unpack2(acc[i][0]), b = unpack2(acc[i][1]);
            float4 cur = *(const float4*)&xs[ph + i][dd0];
            cur.x += a.x + bb.x; cur.y += a.y + bb.y;
            cur.z += b.x + bb.z; cur.w += b.y + bb.w;
            *(float4*)&xs[ph + i][dd0] = cur;
        }
    }
    __syncwarp();
}

// ---------------------------------------------------------------------------
// Warp-level carry attention, FUSED q/k/v (packs shared across 3 matrices).
// ws layout: qs @ 0, ks @ 544, vs @ 1088, each 8 rows of stride 68.
// ---------------------------------------------------------------------------
__device__ __forceinline__ void attn_w(
    float (*xs)[ND], float* ws, float (*sc)[8],
    const float* __restrict__ Wq, const float* __restrict__ Wk,
    const float* __restrict__ Wv, int lane)
{
    const int c0 = lane * 2;
    float* qsm = ws;
    float* ksm = ws + 544;
    float* vsm = ws + 1088;
    {
        ull aq[NP], ak[NP], av[NP];
        #pragma unroll
        for (int p = 0; p < NP; p++) { aq[p] = 0ull; ak[p] = 0ull; av[p] = 0ull; }
        #pragma unroll 2
        for (int d4 = 0; d4 < ND; d4 += 4) {
            ull wq0 = __ldg((const ull*)(Wq + (d4 + 0) * ND + c0));
            ull wq1 = __ldg((const ull*)(Wq + (d4 + 1) * ND + c0));
            ull wq2 = __ldg((const ull*)(Wq + (d4 + 2) * ND + c0));
            ull wq3 = __ldg((const ull*)(Wq + (d4 + 3) * ND + c0));
            ull wk0 = __ldg((const ull*)(Wk + (d4 + 0) * ND + c0));
            ull wk1 = __ldg((const ull*)(Wk + (d4 + 1) * ND + c0));
            ull wk2 = __ldg((const ull*)(Wk + (d4 + 2) * ND + c0));
            ull wk3 = __ldg((const ull*)(Wk + (d4 + 3) * ND + c0));
            ull wv0 = __ldg((const ull*)(Wv + (d4 + 0) * ND + c0));
            ull wv1 = __ldg((const ull*)(Wv + (d4 + 1) * ND + c0));
            ull wv2 = __ldg((const ull*)(Wv + (d4 + 2) * ND + c0));
            ull wv3 = __ldg((const ull*)(Wv + (d4 + 3) * ND + c0));
            #pragma unroll
            for (int p = 0; p < NP; p++) {
                float4 xv = *(const float4*)&xs[p][d4];
                ull xx;
                xx = pack2(xv.x, xv.x);
                aq[p] = fma2(xx, wq0, aq[p]);
                ak[p] = fma2(xx, wk0, ak[p]);
                av[p] = fma2(xx, wv0, av[p]);
                xx = pack2(xv.y, xv.y);
                aq[p] = fma2(xx, wq1, aq[p]);
                ak[p] = fma2(xx, wk1, ak[p]);
                av[p] = fma2(xx, wv1, av[p]);
                xx = pack2(xv.z, xv.z);
                aq[p] = fma2(xx, wq2, aq[p]);
                ak[p] = fma2(xx, wk2, ak[p]);
                av[p] = fma2(xx, wv2, av[p]);
                xx = pack2(xv.w, xv.w);
                aq[p] = fma2(xx, wq3, aq[p]);
                ak[p] = fma2(xx, wk3, ak[p]);
                av[p] = fma2(xx, wv3, av[p]);
            }
        }
        #pragma unroll
        for (int p = 0; p < NP; p++) {
            float2 q = unpack2(aq[p]);
            float2 k = unpack2(ak[p]);
            float2 v = unpack2(av[p]);
            *(float2*)&qsm[p * QK_STRIDE + c0] = q;
            *(float2*)&ksm[p * QK_STRIDE + c0] = k;
            *(float2*)&vsm[p * QK_STRIDE + c0] = v;
        }
    }
    __syncwarp();
    // ---- scores: each lane does 2 of the 64 (p,q') dots ----
    #pragma unroll
    for (int j = 0; j < 2; j++) {
        int idx = lane + 32 * j;
        int p = idx >> 3, qq = idx & 7;
        float s = 0.f;
        #pragma unroll
        for (int d4 = 0; d4 < ND; d4 += 4) {
            float4 qv = *(const float4*)&qsm[p * QK_STRIDE + d4];
            float4 kv = *(const float4*)&ksm[qq * QK_STRIDE + d4];
            s = fmaf(qv.x, kv.x, s); s = fmaf(qv.y, kv.y, s);
            s = fmaf(qv.z, kv.z, s); s = fmaf(qv.w, kv.w, s);
        }
        sc[p][qq] = s * 0.125f;
    }
    __syncwarp();
    // ---- softmax over q' (lanes 0-7, one row each) ----
    if (lane < 8) {
        float m = sc[lane][0];
        #pragma unroll
        for (int q = 1; q < 8; q++) m = fmaxf(m, sc[lane][q]);
        float e[8], sum = 0.f;
        #pragma unroll
        for (int q = 0; q < 8; q++) { e[q] = __expf(sc[lane][q] - m); sum += e[q]; }
        float inv = 1.0f / sum;
        #pragma unroll
        for (int q = 0; q < 8; q++) sc[lane][q] = e[q] * inv;
    }
    __syncwarp();
    // ---- out: xs += s @ v (lane owns column pair c0) ----
    {
        ull vq[8];
        #pragma unroll
        for (int q = 0; q < 8; q++)
            vq[q] = *(const ull*)&vsm[q * QK_STRIDE + c0];
        #pragma unroll
        for (int p = 0; p < NP; p++) {
            float4 s0 = *(const float4*)&sc[p][0];
            float4 s1 = *(const float4*)&sc[p][4];
            ull a = 0ull;
            a = fma2(pack2(s0.x, s0.x), vq[0], a);
            a = fma2(pack2(s0.y, s0.y), vq[1], a);
            a = fma2(pack2(s0.z, s0.z), vq[2], a);
            a = fma2(pack2(s0.w, s0.w), vq[3], a);
            a = fma2(pack2(s1.x, s1.x), vq[4], a);
            a = fma2(pack2(s1.y, s1.y), vq[5], a);
            a = fma2(pack2(s1.z, s1.z), vq[6], a);
            a = fma2(pack2(s1.w, s1.w), vq[7], a);
            float2 r = unpack2(a);
            float2 cur = *(const float2*)&xs[p][c0];
            cur.x += r.x; cur.y += r.y;
            *(float2*)&xs[p][c0] = cur;
        }
    }
    __syncwarp();
}

// ---------------------------------------------------------------------------
// ONE fused compute kernel: four work-stealing pools, heaviest first.
// __launch_bounds__(128, 4): cap regs at 128 (was 136 -> 3 blocks/SM).
// An 8-register ask — expect rematerialization, not spills.
// ---------------------------------------------------------------------------
__global__ void __launch_bounds__(128, 4) fused_kernel(
    const float* __restrict__ xin, float* __restrict__ xout,
    const float* __restrict__ Wi1, const float* __restrict__ bi1,
    const float* __restrict__ Wi2, const float* __restrict__ bi2,
    const float* __restrict__ Wq, const float* __restrict__ Wk,
    const float* __restrict__ Wv,
    const float* __restrict__ Wc1, const float* __restrict__ bc1,
    const float* __restrict__ Wc2, const float* __restrict__ bc2,
    const float* __restrict__ Wd1, const float* __restrict__ bd1,
    const float* __restrict__ Wd2, const float* __restrict__ bd2,
    const float* __restrict__ Wm1, const float* __restrict__ bm1,
    const float* __restrict__ Wm2, const float* __restrict__ bm2,
    const float* __restrict__ Wf1, const float* __restrict__ bf1,
    const float* __restrict__ Wf2, const float* __restrict__ bf2)
{
    __shared__ __align__(16) float xs[4][NP][ND];
    __shared__ __align__(16) float ws[4][WS_STRIDE];
    __shared__ __align__(16) float sc[4][NP][8];
    const int w = threadIdx.x >> 5, lane = threadIdx.x & 31;
    float (*xsr)[ND] = xs[w];
    float* wsr = ws[w];
    float4* mine = (float4*)&xsr[0][0];

    // ---------------- pool 0: carry cascade rows ----------------
    const int n0 = g_cnt[0];
    for (;;) {
        int idx = 0;
        if (lane == 0) idx = atomicAdd(&g_claim[0], 1);
        idx = __shfl_sync(0xffffffffu, idx, 0);
        if (idx >= n0) break;
        const int b = g_carry[idx];
        const int op = g_op[b];
        const float4* src = (const float4*)(xin + (size_t)b * NP * ND);
        #pragma unroll
        for (int j = 0; j < 4; j++) mine[lane + 32 * j] = src[lane + 32 * j];
        __syncwarp();
        ffn_w(xsr, wsr, Wi1 + (size_t)op * ND * NH, bi1 + op * NH,
              Wi2 + (size_t)op * NH * ND, bi2 + op * ND, lane);
        {
            const float* W1 = Wc1 + (size_t)op * ND * NH;
            const float* B1 = bc1 + op * NH;
            const float* W2 = Wc2 + (size_t)op * NH * ND;
            const float* B2 = bc2 + op * ND;
            #pragma unroll 1
            for (int it = 0; it < NCAS; it++) {
                attn_w(xsr, wsr, sc[w], Wq, Wk, Wv, lane);
                ffn_w(xsr, wsr, W1, B1, W2, B2, lane);
            }
        }
        ffn_w(xsr, wsr, Wf1 + (size_t)op * ND * NH, bf1 + op * NH,
              Wf2 + (size_t)op * NH * ND, bf2 + op * ND, lane);
        float4* dst = (float4*)(xout + (size_t)b * NP * ND);
        #pragma unroll
        for (int j = 0; j < 4; j++) dst[lane + 32 * j] = mine[lane + 32 * j];
        __syncwarp();
    }
    // ---------------- pool 1: DIV chain rows ----------------
    const int n1 = g_cnt[1];
    for (;;) {
        int idx = 0;
        if (lane == 0) idx = atomicAdd(&g_claim[1], 1);
        idx = __shfl_sync(0xffffffffu, idx, 0);
        if (idx >= n1) break;
        const int b = g_div[idx];
        const float4* src = (const float4*)(xin + (size_t)b * NP * ND);
        #pragma unroll
        for (int j = 0; j < 4; j++) mine[lane + 32 * j] = src[lane + 32 * j];
        __syncwarp();
        ffn_w(xsr, wsr, Wi1 + (size_t)3 * ND * NH, bi1 + 3 * NH,
              Wi2 + (size_t)3 * NH * ND, bi2 + 3 * ND, lane);
        #pragma unroll 1
        for (int i = 0; i < NITER_; i++)
            ffn_w(xsr, wsr, Wd1 + (size_t)i * ND * NH, bd1 + i * NH,
                  Wd2 + (size_t)i * NH * ND, bd2 + i * ND, lane);
        ffn_w(xsr, wsr, Wf1 + (size_t)3 * ND * NH, bf1 + 3 * NH,
              Wf2 + (size_t)3 * NH * ND, bf2 + 3 * ND, lane);
        float4* dst = (float4*)(xout + (size_t)b * NP * ND);
        #pragma unroll
        for (int j = 0; j < 4; j++) dst[lane + 32 * j] = mine[lane + 32 * j];
        __syncwarp();
    }
    // ---------------- pool 2: MOD chain rows ----------------
    const int n2 = g_cnt[2];
    for (;;) {
        int idx = 0;
        if (lane == 0) idx = atomicAdd(&g_claim[2], 1);
        idx = __shfl_sync(0xffffffffu, idx, 0);
        if (idx >= n2) break;
        const int b = g_mod[idx];
        const float4* src = (const float4*)(xin + (size_t)b * NP * ND);
        #pragma unroll
        for (int j = 0; j < 4; j++) mine[lane + 32 * j] = src[lane + 32 * j];
        __syncwarp();
        ffn_w(xsr, wsr, Wi1 + (size_t)4 * ND * NH, bi1 + 4 * NH,
              Wi2 + (size_t)4 * NH * ND, bi2 + 4 * ND, lane);
        #pragma unroll 1
        for (int i = 0; i < NITER_; i++)
            ffn_w(xsr, wsr, Wm1 + (size_t)i * ND * NH, bm1 + i * NH,
                  Wm2 + (size_t)i * NH * ND, bm2 + i * ND, lane);
        ffn_w(xsr, wsr, Wf1 + (size_t)4 * ND * NH, bf1 + 4 * NH,
              Wf2 + (size_t)4 * NH * ND, bf2 + 4 * ND, lane);
        float4* dst = (float4*)(xout + (size_t)b * NP * ND);
        #pragma unroll
        for (int j = 0; j < 4; j++) dst[lane + 32 * j] = mine[lane + 32 * j];
        __syncwarp();
    }
    // ---------------- pool 3: dense rows (stage1 + final only) ----------------
    const int n3 = g_cnt[3];
    for (;;) {
        int idx = 0;
        if (lane == 0) idx = atomicAdd(&g_claim[3], 1);
        idx = __shfl_sync(0xffffffffu, idx, 0);
        if (idx >= n3) break;
        const int b = g_dense[idx];
        const int op = g_op[b];
        const float4* src = (const float4*)(xin + (size_t)b * NP * ND);
        #pragma unroll
        for (int j = 0; j < 4; j++) mine[lane + 32 * j] = src[lane + 32 * j];
        __syncwarp();
        ffn_w(xsr, wsr, Wi1 + (size_t)op * ND * NH, bi1 + op * NH,
              Wi2 + (size_t)op * NH * ND, bi2 + op * ND, lane);
        ffn_w(xsr, wsr, Wf1 + (size_t)op * ND * NH, bf1 + op * NH,
              Wf2 + (size_t)op * NH * ND, bf2 + op * ND, lane);
        float4* dst = (float4*)(xout + (size_t)b * NP * ND);
        #pragma unroll
        for (int j = 0; j < 4; j++) dst[lane + 32 * j] = mine[lane + 32 * j];
        __syncwarp();
    }
}

// ---------------------------------------------------------------------------
// Launch sequence (graph-capturable; scratch is static device globals).
// 4 launches: route1 -> scan -> route2 -> fused.
// ---------------------------------------------------------------------------
extern "C" void kernel_launch(void* const* d_in, const int* in_sizes, int n_in,
                              void* d_out, int out_size)
{
    const float* x   = (const float*)d_in[0];
    const float* Wi1 = (const float*)d_in[1];
    const float* bi1 = (const float*)d_in[2];
    const float* Wi2 = (const float*)d_in[3];
    const float* bi2 = (const float*)d_in[4];
    const float* Wq  = (const float*)d_in[5];
    const float* Wk  = (const float*)d_in[6];
    const float* Wv  = (const float*)d_in[7];
    const float* Wc1 = (const float*)d_in[8];
    const float* bc1 = (const float*)d_in[9];
    const float* Wc2 = (const float*)d_in[10];
    const float* bc2 = (const float*)d_in[11];
    const float* Wd1 = (const float*)d_in[12];
    const float* bd1 = (const float*)d_in[13];
    const float* Wd2 = (const float*)d_in[14];
    const float* bd2 = (const float*)d_in[15];
    const float* Wm1 = (const float*)d_in[16];
    const float* bm1 = (const float*)d_in[17];
    const float* Wm2 = (const float*)d_in[18];
    const float* bm2 = (const float*)d_in[19];
    const float* Wf1 = (const float*)d_in[20];
    const float* bf1 = (const float*)d_in[21];
    const float* Wf2 = (const float*)d_in[22];
    const float* bf2 = (const float*)d_in[23];
    float* out = (float*)d_out;

    route1_kernel<<<NBLK_R1, 128>>>(x);
    scan_kernel<<<1, 64>>>();
    route2_kernel<<<NB / 128, 128>>>();
    fused_kernel<<<GRID_BLOCKS, 128>>>(
        x, out,
        Wi1, bi1, Wi2, bi2,
        Wq, Wk, Wv, Wc1, bc1, Wc2, bc2,
        Wd1, bd1, Wd2, bd2, Wm1, bm1, Wm2, bm2,
        Wf1, bf1, Wf2, bf2);
}